// round 2
// baseline (speedup 1.0000x reference)
#include <cuda_runtime.h>

// Problem dims
#define NB    8
#define NMAT  256
#define N3    64
#define NF    33                   // real-input FFT: only k = 0..32 needed
#define NPLANE (NMAT * NMAT)       // 65536
#define NTUBES (NB * NPLANE)       // 524288 tubes per tensor
#define NFP    (NB * NF)           // 264 frequency planes

// Scratch (static device allocations; ~138 MB each)
__device__ static float2 g_Af[(size_t)NFP * NPLANE];
__device__ static float2 g_Bf[(size_t)NFP * NPLANE];
__device__ static float2 g_Cf[(size_t)NFP * NPLANE];

// ---------------------------------------------------------------------------
// Forward real DFT along the tube (last) dim, 64-point, k = 0..32.
// Output layout: X[(b*33 + k)*65536 + rowcol]  (frequency-major planes so the
// downstream GEMM sees plain row-major matrices).
// sel = 0 -> g_Af, sel = 1 -> g_Bf.
// ---------------------------------------------------------------------------
__global__ __launch_bounds__(128) void fft_fwd_kernel(const float* __restrict__ x, int sel)
{
    __shared__ float wc[64], ws[64];
    __shared__ float sx[128][N3 + 1];   // +1 pad: conflict-free row reads

    const int tid = threadIdx.x;
    if (tid < 64) {
        float s, c;
        sincospif(tid * (2.0f / 64.0f), &s, &c);   // e^{2*pi*i*tid/64}
        wc[tid] = c; ws[tid] = s;
    }

    // Coalesced staging of 128 tubes (128*64 floats) through shared memory
    const float* src = x + (size_t)blockIdx.x * 128 * N3;
    for (int i = tid; i < 128 * N3; i += 128)
        sx[i >> 6][i & 63] = src[i];
    __syncthreads();

    float xr[64];
#pragma unroll
    for (int t = 0; t < 64; ++t) xr[t] = sx[tid][t];

    const int tube = blockIdx.x * 128 + tid;
    const int b    = tube >> 16;          // / 65536
    const int ij   = tube & 0xFFFF;

    float2* __restrict__ X = sel ? g_Bf : g_Af;

    for (int k = 0; k < NF; ++k) {
        float re = 0.0f, im = 0.0f;
#pragma unroll
        for (int t = 0; t < 64; ++t) {
            const int idx = (k * t) & 63;
            re += xr[t] * wc[idx];        // e^{-i theta}: cos
            im -= xr[t] * ws[idx];        //              -sin
        }
        X[((size_t)(b * NF + k) << 16) + ij] = make_float2(re, im);
    }
}

// ---------------------------------------------------------------------------
// Batched complex GEMM: for each plane p = b*33+k,
//   Cf[p] (256x256) = Af[p] (256x256) * Bf[p] (256x256)
// Tiled 64x64x16, 256 threads, 4x4 complex microtile per thread.
// ---------------------------------------------------------------------------
__global__ __launch_bounds__(256) void cgemm_kernel()
{
    __shared__ float2 As[16][64 + 2];   // [k][m]
    __shared__ float2 Bs[16][64 + 2];   // [k][n]

    const size_t plane = (size_t)blockIdx.z << 16;
    const float2* __restrict__ Ab = g_Af + plane;
    const float2* __restrict__ Bb = g_Bf + plane;
    float2* __restrict__ Cb = g_Cf + plane;

    const int tid = threadIdx.x;
    const int tx = tid & 15;            // 0..15  (n direction)
    const int ty = tid >> 4;            // 0..15  (m direction)
    const int m0 = blockIdx.y * 64;
    const int n0 = blockIdx.x * 64;

    float2 acc[4][4];
#pragma unroll
    for (int i = 0; i < 4; ++i)
#pragma unroll
        for (int j = 0; j < 4; ++j) acc[i][j] = make_float2(0.0f, 0.0f);

    // Load mappings
    const int aml = tid >> 2;           // 0..63   A tile row (m)
    const int ak0 = (tid & 3) * 4;      // 0,4,8,12 A tile col (k) base
    const int bkl = ty;                 // 0..15   B tile row (k)
    const int bn0 = tx * 4;             // 0..60   B tile col (n) base

    for (int k0 = 0; k0 < NMAT; k0 += 16) {
        // A tile: rows m0..m0+63, cols k0..k0+15  (row-major in k) -> As[k][m]
        {
            const float4* ap = reinterpret_cast<const float4*>(
                Ab + (size_t)(m0 + aml) * NMAT + (k0 + ak0));
            const float4 a01 = ap[0];
            const float4 a23 = ap[1];
            As[ak0 + 0][aml] = make_float2(a01.x, a01.y);
            As[ak0 + 1][aml] = make_float2(a01.z, a01.w);
            As[ak0 + 2][aml] = make_float2(a23.x, a23.y);
            As[ak0 + 3][aml] = make_float2(a23.z, a23.w);
        }
        // B tile: rows k0..k0+15, cols n0..n0+63 -> Bs[k][n]
        {
            const float4* bp = reinterpret_cast<const float4*>(
                Bb + (size_t)(k0 + bkl) * NMAT + (n0 + bn0));
            const float4 b01 = bp[0];
            const float4 b23 = bp[1];
            Bs[bkl][bn0 + 0] = make_float2(b01.x, b01.y);
            Bs[bkl][bn0 + 1] = make_float2(b01.z, b01.w);
            Bs[bkl][bn0 + 2] = make_float2(b23.x, b23.y);
            Bs[bkl][bn0 + 3] = make_float2(b23.z, b23.w);
        }
        __syncthreads();

#pragma unroll
        for (int kk = 0; kk < 16; ++kk) {
            float2 a[4], b[4];
#pragma unroll
            for (int i = 0; i < 4; ++i) a[i] = As[kk][ty * 4 + i];
#pragma unroll
            for (int j = 0; j < 4; ++j) b[j] = Bs[kk][tx * 4 + j];
#pragma unroll
            for (int i = 0; i < 4; ++i)
#pragma unroll
                for (int j = 0; j < 4; ++j) {
                    acc[i][j].x += a[i].x * b[j].x;
                    acc[i][j].x -= a[i].y * b[j].y;
                    acc[i][j].y += a[i].x * b[j].y;
                    acc[i][j].y += a[i].y * b[j].x;
                }
        }
        __syncthreads();
    }

    // Epilogue: each row of 4 consecutive complex values = 2 float4 stores
#pragma unroll
    for (int i = 0; i < 4; ++i) {
        float4* cp = reinterpret_cast<float4*>(
            Cb + (size_t)(m0 + ty * 4 + i) * NMAT + (n0 + tx * 4));
        cp[0] = make_float4(acc[i][0].x, acc[i][0].y, acc[i][1].x, acc[i][1].y);
        cp[1] = make_float4(acc[i][2].x, acc[i][2].y, acc[i][3].x, acc[i][3].y);
    }
}

// ---------------------------------------------------------------------------
// Inverse DFT (Hermitian): out[t] = (1/64)*(C0 + (-1)^t*C32
//                                   + 2*sum_{k=1}^{31} (re_k cos - im_k sin))
// ---------------------------------------------------------------------------
__global__ __launch_bounds__(128) void ifft_kernel(float* __restrict__ out)
{
    __shared__ float wc[64], ws[64];
    const int tid = threadIdx.x;
    if (tid < 64) {
        float s, c;
        sincospif(tid * (2.0f / 64.0f), &s, &c);
        wc[tid] = c; ws[tid] = s;
    }
    __syncthreads();

    const int tube = blockIdx.x * 128 + tid;   // (b, i, n)
    const int b    = tube >> 16;
    const int in_  = tube & 0xFFFF;

    float2 cf[NF];
#pragma unroll
    for (int k = 0; k < NF; ++k)
        cf[k] = g_Cf[((size_t)(b * NF + k) << 16) + in_];

    float* dst = out + (size_t)tube * N3;

    for (int t = 0; t < 64; t += 4) {
        float4 r;
        float* rp = &r.x;
#pragma unroll
        for (int q = 0; q < 4; ++q) {
            const int tt = t + q;
            float acc = 0.5f * cf[0].x + ((tt & 1) ? -0.5f : 0.5f) * cf[32].x;
#pragma unroll
            for (int k = 1; k < 32; ++k) {
                const int idx = (k * tt) & 63;
                acc += cf[k].x * wc[idx];
                acc -= cf[k].y * ws[idx];
            }
            rp[q] = acc * (1.0f / 32.0f);
        }
        *reinterpret_cast<float4*>(dst + t) = r;
    }
}

// ---------------------------------------------------------------------------
extern "C" void kernel_launch(void* const* d_in, const int* in_sizes, int n_in,
                              void* d_out, int out_size)
{
    const float* A = (const float*)d_in[0];
    const float* B = (const float*)d_in[1];
    float* out = (float*)d_out;

    const int fftBlocks = NTUBES / 128;          // 4096

    fft_fwd_kernel<<<fftBlocks, 128>>>(A, 0);
    fft_fwd_kernel<<<fftBlocks, 128>>>(B, 1);

    dim3 ggrid(NMAT / 64, NMAT / 64, NFP);       // (4, 4, 264)
    cgemm_kernel<<<ggrid, 256>>>();

    ifft_kernel<<<fftBlocks, 128>>>(out);
}

// round 7
// speedup vs baseline: 1.2603x; 1.2603x over previous
#include <cuda_runtime.h>
#include <cuda_bf16.h>
#include <mma.h>
#include <cstdint>

using namespace nvcuda;

// Problem dims
#define NB    8
#define NMAT  256
#define N3    64
#define NF    33                   // real-input FFT: only k = 0..32 needed
#define NPLANE (NMAT * NMAT)       // 65536
#define NTUBES (NB * NPLANE)       // 524288
#define NFP    (NB * NF)           // 264 frequency planes

#define APLANE (256 * 512)         // A' plane elems (bf16): m x k'
#define BPLANE (512 * 512)         // B' plane elems (bf16): k' x n'

// Scratch (static device allocations)
__device__ static __nv_bfloat16 g_Ah[(size_t)NFP * APLANE];   // 69 MB
__device__ static __nv_bfloat16 g_Al[(size_t)NFP * APLANE];   // 69 MB
__device__ static __nv_bfloat16 g_Bh[(size_t)NFP * BPLANE];   // 138 MB
__device__ static __nv_bfloat16 g_Bl[(size_t)NFP * BPLANE];   // 138 MB
__device__ static float2       g_Cf[(size_t)NFP * NPLANE];    // 138 MB

static __device__ __forceinline__ uint32_t pack2(__nv_bfloat16 a, __nv_bfloat16 b) {
    __nv_bfloat162 t; t.x = a; t.y = b;
    return *reinterpret_cast<uint32_t*>(&t);
}

// ===========================================================================
// Forward real DFT along tube dim (64-pt, k = 0..32), fused bf16 hi/lo split.
// sel=0 (A): writes A'[p][m=i][2j,2j+1] = (re, im)           (hi & lo arrays)
// sel=1 (B): writes B'[p][2i][2j..] = (re, im)
//            and    B'[p][2i+1][2j..] = (-im, re)
// ===========================================================================
__global__ __launch_bounds__(128) void fft_fwd_kernel(const float* __restrict__ x, int sel)
{
    __shared__ float wc[64], ws[64];
    __shared__ float sx[128][N3 + 1];

    const int tid = threadIdx.x;
    if (tid < 64) {
        float s, c;
        sincospif(tid * (2.0f / 64.0f), &s, &c);
        wc[tid] = c; ws[tid] = s;
    }
    const float* src = x + (size_t)blockIdx.x * 128 * N3;
    for (int i = tid; i < 128 * N3; i += 128)
        sx[i >> 6][i & 63] = src[i];
    __syncthreads();

    float xr[64];
#pragma unroll
    for (int t = 0; t < 64; ++t) xr[t] = sx[tid][t];

    const int tube = blockIdx.x * 128 + tid;
    const int b = tube >> 16;
    const int i = (tube >> 8) & 255;     // row index (A: m, B: contraction k)
    const int j = tube & 255;            // col index (A: contraction k, B: n)

    for (int k = 0; k < NF; ++k) {
        float re = 0.0f, im = 0.0f;
#pragma unroll
        for (int t = 0; t < 64; ++t) {
            const int idx = (k * t) & 63;
            re += xr[t] * wc[idx];
            im -= xr[t] * ws[idx];
        }
        const int p = b * NF + k;
        const __nv_bfloat16 rh = __float2bfloat16(re);
        const __nv_bfloat16 ih = __float2bfloat16(im);
        const __nv_bfloat16 rl = __float2bfloat16(re - __bfloat162float(rh));
        const __nv_bfloat16 il = __float2bfloat16(im - __bfloat162float(ih));

        if (sel == 0) {
            const size_t off = (size_t)p * APLANE + (size_t)i * 512 + 2 * j;
            *reinterpret_cast<uint32_t*>(g_Ah + off) = pack2(rh, ih);
            *reinterpret_cast<uint32_t*>(g_Al + off) = pack2(rl, il);
        } else {
            const size_t o0 = (size_t)p * BPLANE + (size_t)(2 * i) * 512 + 2 * j;
            const size_t o1 = o0 + 512;
            *reinterpret_cast<uint32_t*>(g_Bh + o0) = pack2(rh, ih);
            *reinterpret_cast<uint32_t*>(g_Bh + o1) = pack2(__hneg(ih), rh);
            *reinterpret_cast<uint32_t*>(g_Bl + o0) = pack2(rl, il);
            *reinterpret_cast<uint32_t*>(g_Bl + o1) = pack2(__hneg(il), rl);
        }
    }
}

// ===========================================================================
// Batched real GEMM on tensor cores (wmma bf16, 3-term hi/lo split):
//   per plane p: D[256][512] = A'[256][512] * B'[512][512]
// CTA tile 128(m) x 128(n'), 8 warps @ 64x32, K chunks of 16.
// ===========================================================================
__global__ __launch_bounds__(256, 2) void cgemm_wmma_kernel()
{
    __shared__ __nv_bfloat16 Ah[128][24], Al[128][24];   // ldm 24: conflict-free
    __shared__ __nv_bfloat16 Bh[16][136], Bl[16][136];   // ldm 136: conflict-free

    const int p  = blockIdx.x;
    const int m0 = blockIdx.y * 128;
    const int n0 = blockIdx.z * 128;

    const __nv_bfloat16* __restrict__ Abh = g_Ah + (size_t)p * APLANE + (size_t)m0 * 512;
    const __nv_bfloat16* __restrict__ Abl = g_Al + (size_t)p * APLANE + (size_t)m0 * 512;
    const __nv_bfloat16* __restrict__ Bbh = g_Bh + (size_t)p * BPLANE + n0;
    const __nv_bfloat16* __restrict__ Bbl = g_Bl + (size_t)p * BPLANE + n0;
    float* __restrict__ Cp = reinterpret_cast<float*>(g_Cf)
                           + (size_t)p * (256 * 512) + (size_t)m0 * 512 + n0;

    const int tid = threadIdx.x;
    const int wid = tid >> 5;
    const int wm  = wid & 1;        // 2 warps along m
    const int wn  = wid >> 1;       // 4 warps along n

    wmma::fragment<wmma::accumulator, 16, 16, 16, float> acc[4][2];
#pragma unroll
    for (int fm = 0; fm < 4; ++fm)
#pragma unroll
        for (int fn = 0; fn < 2; ++fn)
            wmma::fill_fragment(acc[fm][fn], 0.0f);

    // Load mapping: A tile 128x16 (2 threads/row, 8 bf16 each);
    //               B tile 16x128 (16 threads/row, 8 bf16 each)
    const int ar = tid >> 1;
    const int ac = (tid & 1) * 8;
    const int br = tid >> 4;
    const int bc = (tid & 15) * 8;

    for (int c = 0; c < 32; ++c) {
        const int k0 = c * 16;
        *reinterpret_cast<uint4*>(&Ah[ar][ac]) =
            *reinterpret_cast<const uint4*>(Abh + (size_t)ar * 512 + k0 + ac);
        *reinterpret_cast<uint4*>(&Al[ar][ac]) =
            *reinterpret_cast<const uint4*>(Abl + (size_t)ar * 512 + k0 + ac);
        *reinterpret_cast<uint4*>(&Bh[br][bc]) =
            *reinterpret_cast<const uint4*>(Bbh + (size_t)(k0 + br) * 512 + bc);
        *reinterpret_cast<uint4*>(&Bl[br][bc]) =
            *reinterpret_cast<const uint4*>(Bbl + (size_t)(k0 + br) * 512 + bc);
        __syncthreads();

        wmma::fragment<wmma::matrix_b, 16, 16, 16, __nv_bfloat16, wmma::row_major> fbh[2], fbl[2];
#pragma unroll
        for (int fn = 0; fn < 2; ++fn) {
            wmma::load_matrix_sync(fbh[fn], &Bh[0][wn * 32 + fn * 16], 136);
            wmma::load_matrix_sync(fbl[fn], &Bl[0][wn * 32 + fn * 16], 136);
        }
#pragma unroll
        for (int fm = 0; fm < 4; ++fm) {
            wmma::fragment<wmma::matrix_a, 16, 16, 16, __nv_bfloat16, wmma::row_major> fah, fal;
            wmma::load_matrix_sync(fah, &Ah[wm * 64 + fm * 16][0], 24);
            wmma::load_matrix_sync(fal, &Al[wm * 64 + fm * 16][0], 24);
#pragma unroll
            for (int fn = 0; fn < 2; ++fn) {
                wmma::mma_sync(acc[fm][fn], fah, fbh[fn], acc[fm][fn]);
                wmma::mma_sync(acc[fm][fn], fah, fbl[fn], acc[fm][fn]);
                wmma::mma_sync(acc[fm][fn], fal, fbh[fn], acc[fm][fn]);
            }
        }
        __syncthreads();
    }

#pragma unroll
    for (int fm = 0; fm < 4; ++fm)
#pragma unroll
        for (int fn = 0; fn < 2; ++fn)
            wmma::store_matrix_sync(Cp + (size_t)(wm * 64 + fm * 16) * 512 + wn * 32 + fn * 16,
                                    acc[fm][fn], 512, wmma::mem_row_major);
}

// ===========================================================================
// Inverse DFT (Hermitian) -> real output
// ===========================================================================
__global__ __launch_bounds__(128) void ifft_kernel(float* __restrict__ out)
{
    __shared__ float wc[64], ws[64];
    const int tid = threadIdx.x;
    if (tid < 64) {
        float s, c;
        sincospif(tid * (2.0f / 64.0f), &s, &c);
        wc[tid] = c; ws[tid] = s;
    }
    __syncthreads();

    const int tube = blockIdx.x * 128 + tid;
    const int b    = tube >> 16;
    const int in_  = tube & 0xFFFF;

    float2 cf[NF];
#pragma unroll
    for (int k = 0; k < NF; ++k)
        cf[k] = g_Cf[((size_t)(b * NF + k) << 16) + in_];

    float* dst = out + (size_t)tube * N3;

    for (int t = 0; t < 64; t += 4) {
        float4 r;
        float* rp = &r.x;
#pragma unroll
        for (int q = 0; q < 4; ++q) {
            const int tt = t + q;
            float acc = 0.5f * cf[0].x + ((tt & 1) ? -0.5f : 0.5f) * cf[32].x;
#pragma unroll
            for (int k = 1; k < 32; ++k) {
                const int idx = (k * tt) & 63;
                acc += cf[k].x * wc[idx];
                acc -= cf[k].y * ws[idx];
            }
            rp[q] = acc * (1.0f / 32.0f);
        }
        *reinterpret_cast<float4*>(dst + t) = r;
    }
}

// ===========================================================================
extern "C" void kernel_launch(void* const* d_in, const int* in_sizes, int n_in,
                              void* d_out, int out_size)
{
    const float* A = (const float*)d_in[0];
    const float* B = (const float*)d_in[1];
    float* out = (float*)d_out;

    const int fftBlocks = NTUBES / 128;          // 4096
    fft_fwd_kernel<<<fftBlocks, 128>>>(A, 0);
    fft_fwd_kernel<<<fftBlocks, 128>>>(B, 1);

    dim3 ggrid(NFP, 2, 4);                       // (264 planes, 2 m-tiles, 4 n-tiles)
    cgemm_wmma_kernel<<<ggrid, 256>>>();

    ifft_kernel<<<fftBlocks, 128>>>(out);
}

// round 10
// speedup vs baseline: 2.3986x; 1.9031x over previous
#include <cuda_runtime.h>
#include <cuda_bf16.h>
#include <mma.h>
#include <cstdint>

using namespace nvcuda;

// Problem dims
#define NB    8
#define NMAT  256
#define N3    64
#define NF    33
#define NPLANE (NMAT * NMAT)       // 65536
#define NTUBES (NB * NPLANE)       // 524288
#define NFP    (NB * NF)           // 264

#define APLANE (256 * 512)
#define BPLANE (512 * 512)

// Scratch
__device__ static __nv_bfloat16 g_Ah[(size_t)NFP * APLANE];
__device__ static __nv_bfloat16 g_Al[(size_t)NFP * APLANE];
__device__ static __nv_bfloat16 g_Bh[(size_t)NFP * BPLANE];
__device__ static __nv_bfloat16 g_Bl[(size_t)NFP * BPLANE];
__device__ static float2       g_Cf[(size_t)NFP * NPLANE];

// ---------------------------------------------------------------------------
// Compile-time twiddles (device-qualified: no --expt-relaxed-constexpr needed)
// ---------------------------------------------------------------------------
__device__ constexpr float TW32R[16] = {
    1.0f, 0.980785280403230449f, 0.923879532511286756f, 0.831469612302545237f,
    0.707106781186547524f, 0.555570233019602225f, 0.382683432365089772f,
    0.195090322016128268f, 0.0f, -0.195090322016128268f, -0.382683432365089772f,
    -0.555570233019602225f, -0.707106781186547524f, -0.831469612302545237f,
    -0.923879532511286756f, -0.980785280403230449f };
__device__ constexpr float TW32I[16] = {
    0.0f, 0.195090322016128268f, 0.382683432365089772f, 0.555570233019602225f,
    0.707106781186547524f, 0.831469612302545237f, 0.923879532511286756f,
    0.980785280403230449f, 1.0f, 0.980785280403230449f, 0.923879532511286756f,
    0.831469612302545237f, 0.707106781186547524f, 0.555570233019602225f,
    0.382683432365089772f, 0.195090322016128268f };
__device__ constexpr float W64R[33] = {
    1.0f, 0.995184726672196886f, 0.980785280403230449f, 0.956940335732208865f,
    0.923879532511286756f, 0.881921264348355030f, 0.831469612302545237f,
    0.773010453362736961f, 0.707106781186547524f, 0.634393284163645498f,
    0.555570233019602225f, 0.471396736825997649f, 0.382683432365089772f,
    0.290284677254462368f, 0.195090322016128268f, 0.098017140329560602f,
    0.0f, -0.098017140329560602f, -0.195090322016128268f, -0.290284677254462368f,
    -0.382683432365089772f, -0.471396736825997649f, -0.555570233019602225f,
    -0.634393284163645498f, -0.707106781186547524f, -0.773010453362736961f,
    -0.831469612302545237f, -0.881921264348355030f, -0.923879532511286756f,
    -0.956940335732208865f, -0.980785280403230449f, -0.995184726672196886f, -1.0f };
__device__ constexpr float W64I[33] = {
    0.0f, 0.098017140329560602f, 0.195090322016128268f, 0.290284677254462368f,
    0.382683432365089772f, 0.471396736825997649f, 0.555570233019602225f,
    0.634393284163645498f, 0.707106781186547524f, 0.773010453362736961f,
    0.831469612302545237f, 0.881921264348355030f, 0.923879532511286756f,
    0.956940335732208865f, 0.980785280403230449f, 0.995184726672196886f,
    1.0f, 0.995184726672196886f, 0.980785280403230449f, 0.956940335732208865f,
    0.923879532511286756f, 0.881921264348355030f, 0.831469612302545237f,
    0.773010453362736961f, 0.707106781186547524f, 0.634393284163645498f,
    0.555570233019602225f, 0.471396736825997649f, 0.382683432365089772f,
    0.290284677254462368f, 0.195090322016128268f, 0.098017140329560602f, 0.0f };
__device__ constexpr int BR5[32] = {
    0,16,8,24,4,20,12,28,2,18,10,26,6,22,14,30,
    1,17,9,25,5,21,13,29,3,19,11,27,7,23,15,31 };

// 32-point DIF FFT, natural in, bit-reversed out. SIGN=+1 inverse, -1 forward.
template<int M, int SIGN>
static __device__ __forceinline__ void fft32_stage(float* zr, float* zi) {
    constexpr int H = M / 2;
#pragma unroll
    for (int g = 0; g < 32; g += M)
#pragma unroll
        for (int j = 0; j < H; ++j) {
            const float wr = TW32R[j * (32 / M)];
            const float wi = SIGN * TW32I[j * (32 / M)];
            const int i0 = g + j, i1 = g + j + H;
            const float ar = zr[i0], ai = zi[i0];
            const float br_ = zr[i1], bi = zi[i1];
            zr[i0] = ar + br_;  zi[i0] = ai + bi;
            const float dr = ar - br_, di = ai - bi;
            zr[i1] = dr * wr - di * wi;
            zi[i1] = dr * wi + di * wr;
        }
}
template<int SIGN>
static __device__ __forceinline__ void fft32(float* zr, float* zi) {
    fft32_stage<32, SIGN>(zr, zi);
    fft32_stage<16, SIGN>(zr, zi);
    fft32_stage<8,  SIGN>(zr, zi);
    fft32_stage<4,  SIGN>(zr, zi);
    fft32_stage<2,  SIGN>(zr, zi);
}

static __device__ __forceinline__ uint32_t pack2(__nv_bfloat16 a, __nv_bfloat16 b) {
    __nv_bfloat162 t; t.x = a; t.y = b;
    return *reinterpret_cast<uint32_t*>(&t);
}

// ===========================================================================
// Forward rfft64 (k=0..32) via complex FFT32, fused bf16 hi/lo split + pack.
// ===========================================================================
__global__ __launch_bounds__(128) void fft_fwd_kernel(const float* __restrict__ x, int sel)
{
    __shared__ float sx[128][N3 + 1];
    const int tid = threadIdx.x;

    const float* src = x + (size_t)blockIdx.x * 128 * N3;
    for (int i = tid; i < 128 * N3; i += 128)
        sx[i >> 6][i & 63] = src[i];
    __syncthreads();

    float zr[32], zi[32];
#pragma unroll
    for (int n = 0; n < 32; ++n) {
        zr[n] = sx[tid][2 * n];
        zi[n] = sx[tid][2 * n + 1];
    }
    fft32<-1>(zr, zi);   // forward; output bit-reversed

    const int tube = blockIdx.x * 128 + tid;
    const int b = tube >> 16;
    const int i = (tube >> 8) & 255;
    const int j = tube & 255;

#pragma unroll
    for (int k = 0; k <= 32; ++k) {
        float Xr, Xi;
        if (k == 0 || k == 32) {
            const float e = zr[0], o = zi[0];       // Z[0] = (Re, Im)
            Xr = (k == 0) ? (e + o) : (e - o);
            Xi = 0.0f;
        } else {
            const float Zkr = zr[BR5[k]],          Zki = zi[BR5[k]];
            const float Zcr = zr[BR5[(32 - k) & 31]], Zci = -zi[BR5[(32 - k) & 31]];
            const float Er = 0.5f * (Zkr + Zcr), Ei = 0.5f * (Zki + Zci);
            const float Dr = 0.5f * (Zkr - Zcr), Di = 0.5f * (Zki - Zci);
            const float Or = Di, Oi = -Dr;          // O = -i*D
            // X = E + (c, -s) * O
            Xr = Er + W64R[k] * Or + W64I[k] * Oi;
            Xi = Ei + W64R[k] * Oi - W64I[k] * Or;
        }

        const int p = b * NF + k;
        const __nv_bfloat16 rh = __float2bfloat16(Xr);
        const __nv_bfloat16 ih = __float2bfloat16(Xi);
        const __nv_bfloat16 rl = __float2bfloat16(Xr - __bfloat162float(rh));
        const __nv_bfloat16 il = __float2bfloat16(Xi - __bfloat162float(ih));

        if (sel == 0) {
            const size_t off = (size_t)p * APLANE + (size_t)i * 512 + 2 * j;
            *reinterpret_cast<uint32_t*>(g_Ah + off) = pack2(rh, ih);
            *reinterpret_cast<uint32_t*>(g_Al + off) = pack2(rl, il);
        } else {
            const size_t o0 = (size_t)p * BPLANE + (size_t)(2 * i) * 512 + 2 * j;
            const size_t o1 = o0 + 512;
            *reinterpret_cast<uint32_t*>(g_Bh + o0) = pack2(rh, ih);
            *reinterpret_cast<uint32_t*>(g_Bh + o1) = pack2(__hneg(ih), rh);
            *reinterpret_cast<uint32_t*>(g_Bl + o0) = pack2(rl, il);
            *reinterpret_cast<uint32_t*>(g_Bl + o1) = pack2(__hneg(il), rl);
        }
    }
}

// ===========================================================================
// Batched bf16 wmma GEMM with cp.async double buffering.
//   per plane: D[256][512] = A'[256][512] * B'[512][512], 3-term hi/lo split
// ===========================================================================
#define CP_ASYNC16(dst, src) \
    asm volatile("cp.async.cg.shared.global [%0], [%1], 16;" :: "r"(dst), "l"(src) : "memory")
#define CP_COMMIT() asm volatile("cp.async.commit_group;" ::: "memory")
#define CP_WAIT1()  asm volatile("cp.async.wait_group 1;" ::: "memory")
#define CP_WAIT0()  asm volatile("cp.async.wait_group 0;" ::: "memory")

__global__ __launch_bounds__(256, 2) void cgemm_wmma_kernel()
{
    __shared__ __nv_bfloat16 Ah[2][128][24], Al[2][128][24];
    __shared__ __nv_bfloat16 Bh[2][16][136], Bl[2][16][136];

    const int p  = blockIdx.x;
    const int m0 = blockIdx.y * 128;
    const int n0 = blockIdx.z * 128;

    const __nv_bfloat16* __restrict__ Abh = g_Ah + (size_t)p * APLANE + (size_t)m0 * 512;
    const __nv_bfloat16* __restrict__ Abl = g_Al + (size_t)p * APLANE + (size_t)m0 * 512;
    const __nv_bfloat16* __restrict__ Bbh = g_Bh + (size_t)p * BPLANE + n0;
    const __nv_bfloat16* __restrict__ Bbl = g_Bl + (size_t)p * BPLANE + n0;
    float* __restrict__ Cp = reinterpret_cast<float*>(g_Cf)
                           + (size_t)p * (256 * 512) + (size_t)m0 * 512 + n0;

    const int tid = threadIdx.x;
    const int wid = tid >> 5;
    const int wm  = wid & 1;
    const int wn  = wid >> 1;

    const int ar = tid >> 1;
    const int ac = (tid & 1) * 8;
    const int br = tid >> 4;
    const int bc = (tid & 15) * 8;

    const uint32_t sAh = (uint32_t)__cvta_generic_to_shared(&Ah[0][ar][ac]);
    const uint32_t sAl = (uint32_t)__cvta_generic_to_shared(&Al[0][ar][ac]);
    const uint32_t sBh = (uint32_t)__cvta_generic_to_shared(&Bh[0][br][bc]);
    const uint32_t sBl = (uint32_t)__cvta_generic_to_shared(&Bl[0][br][bc]);
    const uint32_t stA = 128 * 24 * 2;    // bytes per A stage
    const uint32_t stB = 16 * 136 * 2;    // bytes per B stage

    const __nv_bfloat16* gAh = Abh + (size_t)ar * 512 + ac;
    const __nv_bfloat16* gAl = Abl + (size_t)ar * 512 + ac;
    const __nv_bfloat16* gBh = Bbh + (size_t)br * 512 + bc;
    const __nv_bfloat16* gBl = Bbl + (size_t)br * 512 + bc;

#define LOAD_CHUNK(st, c) do {                                  \
        const int _k0 = (c) * 16;                               \
        CP_ASYNC16(sAh + (st) * stA, gAh + _k0);                \
        CP_ASYNC16(sAl + (st) * stA, gAl + _k0);                \
        CP_ASYNC16(sBh + (st) * stB, gBh + (size_t)_k0 * 512);  \
        CP_ASYNC16(sBl + (st) * stB, gBl + (size_t)_k0 * 512);  \
        CP_COMMIT();                                            \
    } while (0)

    wmma::fragment<wmma::accumulator, 16, 16, 16, float> acc[4][2];
#pragma unroll
    for (int fm = 0; fm < 4; ++fm)
#pragma unroll
        for (int fn = 0; fn < 2; ++fn)
            wmma::fill_fragment(acc[fm][fn], 0.0f);

    LOAD_CHUNK(0, 0);
    LOAD_CHUNK(1, 1);

    for (int c = 0; c < 32; ++c) {
        const int st = c & 1;
        if (c == 31) { CP_WAIT0(); } else { CP_WAIT1(); }
        __syncthreads();

        wmma::fragment<wmma::matrix_b, 16, 16, 16, __nv_bfloat16, wmma::row_major> fbh[2], fbl[2];
#pragma unroll
        for (int fn = 0; fn < 2; ++fn) {
            wmma::load_matrix_sync(fbh[fn], &Bh[st][0][wn * 32 + fn * 16], 136);
            wmma::load_matrix_sync(fbl[fn], &Bl[st][0][wn * 32 + fn * 16], 136);
        }
#pragma unroll
        for (int fm = 0; fm < 4; ++fm) {
            wmma::fragment<wmma::matrix_a, 16, 16, 16, __nv_bfloat16, wmma::row_major> fah, fal;
            wmma::load_matrix_sync(fah, &Ah[st][wm * 64 + fm * 16][0], 24);
            wmma::load_matrix_sync(fal, &Al[st][wm * 64 + fm * 16][0], 24);
#pragma unroll
            for (int fn = 0; fn < 2; ++fn) {
                wmma::mma_sync(acc[fm][fn], fah, fbh[fn], acc[fm][fn]);
                wmma::mma_sync(acc[fm][fn], fah, fbl[fn], acc[fm][fn]);
                wmma::mma_sync(acc[fm][fn], fal, fbh[fn], acc[fm][fn]);
            }
        }
        __syncthreads();
        if (c + 2 < 32) LOAD_CHUNK(st, c + 2);
    }

#pragma unroll
    for (int fm = 0; fm < 4; ++fm)
#pragma unroll
        for (int fn = 0; fn < 2; ++fn)
            wmma::store_matrix_sync(Cp + (size_t)(wm * 64 + fm * 16) * 512 + wn * 32 + fn * 16,
                                    acc[fm][fn], 512, wmma::mem_row_major);
}

// ===========================================================================
// Inverse: Hermitian spectrum -> real 64, via complex iFFT32 in registers.
// ===========================================================================
__global__ __launch_bounds__(128) void ifft_kernel(float* __restrict__ out)
{
    const int tube = blockIdx.x * 128 + threadIdx.x;
    const int b    = tube >> 16;
    const int in_  = tube & 0xFFFF;

    float zr[32], zi[32];
    const float h = 1.0f / 64.0f;

    // k = 0 / 32
    {
        const float2 X0  = g_Cf[((size_t)(b * NF + 0)  << 16) + in_];
        const float2 X32 = g_Cf[((size_t)(b * NF + 32) << 16) + in_];
        const float Er = (X0.x + X32.x) * h, Ei = (X0.y + X32.y) * h;
        const float Or = (X0.x - X32.x) * h, Oi = (X0.y - X32.y) * h;
        zr[0] = Er - Oi;
        zi[0] = Ei + Or;
    }
    // pairs (k, 32-k), k = 1..16
#pragma unroll
    for (int k = 1; k <= 16; ++k) {
        const float2 Xk = g_Cf[((size_t)(b * NF + k)        << 16) + in_];
        const float2 Xq = g_Cf[((size_t)(b * NF + (32 - k)) << 16) + in_];
        const float Er = (Xk.x + Xq.x) * h, Ei = (Xk.y - Xq.y) * h;
        const float Dr = (Xk.x - Xq.x) * h, Di = (Xk.y + Xq.y) * h;
        const float Or = Dr * W64R[k] - Di * W64I[k];
        const float Oi = Dr * W64I[k] + Di * W64R[k];
        zr[k] = Er - Oi;            // Z[k]
        zi[k] = Ei + Or;
        if (k < 16) {               // Z[32-k] = conj(E) + i*conj(O)
            zr[32 - k] = Er + Oi;
            zi[32 - k] = Or - Ei;
        }
    }

    fft32<1>(zr, zi);   // unnormalized inverse; output bit-reversed

    float* dst = out + (size_t)tube * N3;
#pragma unroll
    for (int n = 0; n < 32; n += 2) {
        const int p0 = BR5[n], p1 = BR5[n + 1];
        *reinterpret_cast<float4*>(dst + 2 * n) =
            make_float4(zr[p0], zi[p0], zr[p1], zi[p1]);
    }
}

// ===========================================================================
extern "C" void kernel_launch(void* const* d_in, const int* in_sizes, int n_in,
                              void* d_out, int out_size)
{
    const float* A = (const float*)d_in[0];
    const float* B = (const float*)d_in[1];
    float* out = (float*)d_out;

    const int fftBlocks = NTUBES / 128;          // 4096
    fft_fwd_kernel<<<fftBlocks, 128>>>(A, 0);
    fft_fwd_kernel<<<fftBlocks, 128>>>(B, 1);

    dim3 ggrid(NFP, 2, 4);                       // 2112 CTAs
    cgemm_wmma_kernel<<<ggrid, 256>>>();

    ifft_kernel<<<fftBlocks, 128>>>(out);
}